// round 1
// baseline (speedup 1.0000x reference)
#include <cuda_runtime.h>

#define DIMC 1024
#define HEADS 16
#define DH 64
#define BATCHB 4
#define SEQN 2048
#define SCALE 0.125f
#define MASK_VAL -10000000.0f

// Scratch (no allocations allowed): qkv = 100.7MB, x = 33.6MB
__device__ float g_qkv[(size_t)BATCHB * SEQN * 3 * DIMC];
__device__ float g_x[(size_t)BATCHB * SEQN * DIMC];

// ---------------------------------------------------------------------------
// C[m,n] = sum_k A[m,k]*B[n,k] (+bias[n]).  A:[M,K] row-major, B:[N,K] row-major.
// 128x128 block, BK=8, 256 threads, 8x8 micro-tile with +-64 split layout.
// ---------------------------------------------------------------------------
__global__ __launch_bounds__(256) void gemm_nt(const float* __restrict__ A,
                                               const float* __restrict__ B,
                                               float* __restrict__ C,
                                               const float* __restrict__ bias,
                                               int M, int N, int K)
{
    __shared__ float As[8][132];
    __shared__ float Bs[8][132];
    const int t  = threadIdx.x;
    const int bm = blockIdx.y * 128;
    const int bn = blockIdx.x * 128;
    const int ty = t >> 4;
    const int tx = t & 15;
    const int lr = t >> 1;          // 0..127
    const int lc = (t & 1) << 2;    // 0 or 4

    const float* Ap = A + (size_t)(bm + lr) * K + lc;
    const float* Bp = B + (size_t)(bn + lr) * K + lc;

    float acc[8][8];
#pragma unroll
    for (int i = 0; i < 8; i++)
#pragma unroll
        for (int j = 0; j < 8; j++) acc[i][j] = 0.0f;

    for (int k0 = 0; k0 < K; k0 += 8) {
        float4 av = *(const float4*)(Ap + k0);
        float4 bv = *(const float4*)(Bp + k0);
        __syncthreads();
        As[lc + 0][lr] = av.x; As[lc + 1][lr] = av.y;
        As[lc + 2][lr] = av.z; As[lc + 3][lr] = av.w;
        Bs[lc + 0][lr] = bv.x; Bs[lc + 1][lr] = bv.y;
        Bs[lc + 2][lr] = bv.z; Bs[lc + 3][lr] = bv.w;
        __syncthreads();
#pragma unroll
        for (int kk = 0; kk < 8; kk++) {
            float a[8], b[8];
            *(float4*)&a[0] = *(const float4*)&As[kk][ty * 4];
            *(float4*)&a[4] = *(const float4*)&As[kk][ty * 4 + 64];
            *(float4*)&b[0] = *(const float4*)&Bs[kk][tx * 4];
            *(float4*)&b[4] = *(const float4*)&Bs[kk][tx * 4 + 64];
#pragma unroll
            for (int i = 0; i < 8; i++)
#pragma unroll
                for (int j = 0; j < 8; j++)
                    acc[i][j] += a[i] * b[j];
        }
    }

#pragma unroll
    for (int i = 0; i < 8; i++) {
        int row = bm + ((i < 4) ? (ty * 4 + i) : (64 + ty * 4 + i - 4));
        float* Cp = C + (size_t)row * N + bn;
#pragma unroll
        for (int jg = 0; jg < 2; jg++) {
            int col = tx * 4 + jg * 64;
            float4 v;
            v.x = acc[i][jg * 4 + 0];
            v.y = acc[i][jg * 4 + 1];
            v.z = acc[i][jg * 4 + 2];
            v.w = acc[i][jg * 4 + 3];
            if (bias != nullptr) {
                v.x += bias[bn + col + 0];
                v.y += bias[bn + col + 1];
                v.z += bias[bn + col + 2];
                v.w += bias[bn + col + 3];
            }
            *(float4*)(Cp + col) = v;
        }
    }
}

// ---------------------------------------------------------------------------
// Flash attention, fp32. One block = one (b, h, 64-row q-tile).
// qkv layout: row (b*SEQN+n), col s*DIMC + h*DH + d  (s = 0:q, 1:k, 2:v)
// out x layout: [b, n, h, d] contiguous -> (B,N,C)
// ---------------------------------------------------------------------------
__global__ __launch_bounds__(256) void attn_kernel(const float* __restrict__ qkv,
                                                   const int* __restrict__ pmask,
                                                   float* __restrict__ xout)
{
    __shared__ float Qs[64][68];   // [d][r]  (transposed)
    __shared__ float Ks[64][36];   // [d][c]  (transposed), 32 cols
    __shared__ float Vs[32][68];   // [k][d]
    __shared__ float Ps[32][68];   // [k][r]  (transposed)
    __shared__ float mk[32];

    const int t     = threadIdx.x;
    const int qbase = blockIdx.x * 64;
    const int h     = blockIdx.y;
    const int b     = blockIdx.z;

    // Load Q tile transposed
    {
        int r  = t >> 2;            // 0..63
        int d0 = (t & 3) * 16;
        const float* qp = qkv + (size_t)(b * SEQN + qbase + r) * (3 * DIMC) + h * DH + d0;
#pragma unroll
        for (int ii = 0; ii < 4; ii++) {
            float4 v = *(const float4*)(qp + ii * 4);
            int d = d0 + ii * 4;
            Qs[d + 0][r] = v.x; Qs[d + 1][r] = v.y;
            Qs[d + 2][r] = v.z; Qs[d + 3][r] = v.w;
        }
    }

    const int ty = t >> 4;   // 0..15 -> rows ty*4..+4
    const int tx = t & 15;   // 0..15 -> S cols tx*2..+2, O cols tx*4..+4

    float m_old[4], l[4], o[4][4];
#pragma unroll
    for (int i = 0; i < 4; i++) {
        m_old[i] = -3.0e38f;
        l[i] = 0.0f;
#pragma unroll
        for (int j = 0; j < 4; j++) o[i][j] = 0.0f;
    }

    for (int kb = 0; kb < SEQN; kb += 32) {
        __syncthreads();
        // Load K tile transposed: c = t>>3 (0..31), d0 = (t&7)*8
        {
            int c  = t >> 3;
            int d0 = (t & 7) * 8;
            const float* kp = qkv + (size_t)(b * SEQN + kb + c) * (3 * DIMC) + DIMC + h * DH + d0;
#pragma unroll
            for (int ii = 0; ii < 2; ii++) {
                float4 v = *(const float4*)(kp + ii * 4);
                int d = d0 + ii * 4;
                Ks[d + 0][c] = v.x; Ks[d + 1][c] = v.y;
                Ks[d + 2][c] = v.z; Ks[d + 3][c] = v.w;
            }
        }
        // Load V tile natural: k = t>>3, d0 = (t&7)*8
        {
            int kk = t >> 3;
            int d0 = (t & 7) * 8;
            const float* vp = qkv + (size_t)(b * SEQN + kb + kk) * (3 * DIMC) + 2 * DIMC + h * DH + d0;
            *(float4*)&Vs[kk][d0]     = *(const float4*)vp;
            *(float4*)&Vs[kk][d0 + 4] = *(const float4*)(vp + 4);
        }
        if (t < 32) mk[t] = (pmask[b * SEQN + kb + t] > 0) ? 1.0f : 0.0f;
        __syncthreads();

        // S = Q K^T  (64 rows x 32 cols), thread: 4 rows x 2 cols
        float s[4][2];
#pragma unroll
        for (int i = 0; i < 4; i++) { s[i][0] = 0.0f; s[i][1] = 0.0f; }
#pragma unroll 16
        for (int d = 0; d < 64; d++) {
            float a[4];
            *(float4*)a = *(const float4*)&Qs[d][ty * 4];
            float k0 = Ks[d][tx * 2];
            float k1 = Ks[d][tx * 2 + 1];
#pragma unroll
            for (int i = 0; i < 4; i++) {
                s[i][0] += a[i] * k0;
                s[i][1] += a[i] * k1;
            }
        }

        const float mv0 = mk[tx * 2];
        const float mv1 = mk[tx * 2 + 1];
#pragma unroll
        for (int i = 0; i < 4; i++) {
            s[i][0] = (mv0 > 0.5f) ? MASK_VAL : s[i][0] * SCALE;
            s[i][1] = (mv1 > 0.5f) ? MASK_VAL : s[i][1] * SCALE;
        }

        // Online softmax, per row; row-group = 16 lanes sharing ty
#pragma unroll
        for (int i = 0; i < 4; i++) {
            float mt = fmaxf(s[i][0], s[i][1]);
#pragma unroll
            for (int off = 8; off >= 1; off >>= 1)
                mt = fmaxf(mt, __shfl_xor_sync(0xffffffffu, mt, off, 16));
            float mn    = fmaxf(m_old[i], mt);
            float alpha = __expf(m_old[i] - mn);
            float p0 = __expf(s[i][0] - mn);
            float p1 = __expf(s[i][1] - mn);
            float ls = p0 + p1;
#pragma unroll
            for (int off = 8; off >= 1; off >>= 1)
                ls += __shfl_xor_sync(0xffffffffu, ls, off, 16);
            l[i]     = l[i] * alpha + ls;
            m_old[i] = mn;
#pragma unroll
            for (int j = 0; j < 4; j++) o[i][j] *= alpha;
            Ps[tx * 2 + 0][ty * 4 + i] = p0;
            Ps[tx * 2 + 1][ty * 4 + i] = p1;
        }
        __syncthreads();

        // O += P V  (64 rows x 64 d-cols), thread: 4 rows x 4 cols
#pragma unroll 8
        for (int k2 = 0; k2 < 32; k2++) {
            float p[4], v[4];
            *(float4*)p = *(const float4*)&Ps[k2][ty * 4];
            *(float4*)v = *(const float4*)&Vs[k2][tx * 4];
#pragma unroll
            for (int i = 0; i < 4; i++)
#pragma unroll
                for (int j = 0; j < 4; j++)
                    o[i][j] += p[i] * v[j];
        }
    }

    // Epilogue: normalize and store to x[b, n, h, d]
#pragma unroll
    for (int i = 0; i < 4; i++) {
        float inv = 1.0f / l[i];
        int r = qbase + ty * 4 + i;
        float4 v;
        v.x = o[i][0] * inv; v.y = o[i][1] * inv;
        v.z = o[i][2] * inv; v.w = o[i][3] * inv;
        *(float4*)(xout + ((size_t)(b * SEQN + r) * HEADS + h) * DH + tx * 4) = v;
    }
}

// ---------------------------------------------------------------------------
extern "C" void kernel_launch(void* const* d_in, const int* in_sizes, int n_in,
                              void* d_out, int out_size)
{
    const float* x     = (const float*)d_in[0];
    const float* Wqkv  = (const float*)d_in[1];
    const float* Wfc   = (const float*)d_in[2];
    const float* bfc   = (const float*)d_in[3];
    const int*   pmask = (const int*)d_in[4];
    float* out = (float*)d_out;

    float *qkv, *xa;
    cudaGetSymbolAddress((void**)&qkv, g_qkv);
    cudaGetSymbolAddress((void**)&xa, g_x);

    const int M = BATCHB * SEQN;  // 8192

    // 1) qkv = X @ Wqkv^T   (M x 3072)
    gemm_nt<<<dim3(3 * DIMC / 128, M / 128), 256>>>(x, Wqkv, qkv, nullptr, M, 3 * DIMC, DIMC);

    // 2) flash attention -> xa (M x 1024, [b,n,h,d])
    attn_kernel<<<dim3(SEQN / 64, HEADS, BATCHB), 256>>>(qkv, pmask, xa);

    // 3) out = xa @ Wfc^T + b_fc
    gemm_nt<<<dim3(DIMC / 128, M / 128), 256>>>(xa, Wfc, out, bfc, M, DIMC, DIMC);
}

// round 3
// speedup vs baseline: 1.3853x; 1.3853x over previous
#include <cuda_runtime.h>
#include <cstdint>

#define DIMC 1024
#define HEADS 16
#define DH 64
#define BATCHB 4
#define SEQN 2048
#define SCALE 0.125f
#define MASK_VAL -10000000.0f

// Scratch (no allocations allowed)
__device__ float g_qkv[(size_t)BATCHB * SEQN * 3 * DIMC];
__device__ float g_x[(size_t)BATCHB * SEQN * DIMC];

__device__ __forceinline__ uint32_t f2tf32(float x) {
    uint32_t r;
    asm("cvt.rna.tf32.f32 %0, %1;" : "=r"(r) : "f"(x));
    return r;
}

__device__ __forceinline__ void mma_tf32(float* d, const uint32_t* a, const uint32_t* b) {
    asm volatile(
        "mma.sync.aligned.m16n8k8.row.col.f32.tf32.tf32.f32 "
        "{%0,%1,%2,%3}, {%4,%5,%6,%7}, {%8,%9}, {%0,%1,%2,%3};"
        : "+f"(d[0]), "+f"(d[1]), "+f"(d[2]), "+f"(d[3])
        : "r"(a[0]), "r"(a[1]), "r"(a[2]), "r"(a[3]),
          "r"(b[0]), "r"(b[1]));
}

// ---------------------------------------------------------------------------
// C[m,n] = sum_k A[m,k]*B[n,k] (+bias).  TF32 tensor-core version.
// Block 128x128, BK=32, 256 threads (8 warps as 2m x 4n), warp tile 64x32.
// ---------------------------------------------------------------------------
__global__ __launch_bounds__(256) void gemm_nt_tf32(const float* __restrict__ A,
                                                    const float* __restrict__ B,
                                                    float* __restrict__ C,
                                                    const float* __restrict__ bias,
                                                    int M, int N, int K)
{
    __shared__ uint32_t As[128][36];
    __shared__ uint32_t Bs[128][36];

    const int tid  = threadIdx.x;
    const int wid  = tid >> 5;
    const int lane = tid & 31;
    const int g    = lane >> 2;   // groupID 0..7
    const int tg   = lane & 3;    // thread-in-group 0..3
    const int bm   = blockIdx.y * 128;
    const int bn   = blockIdx.x * 128;
    const int wm   = (wid >> 2) * 64;   // warp m-offset 0/64
    const int wn   = (wid & 3) * 32;    // warp n-offset 0/32/64/96

    const int lrow = tid >> 3;          // 0..31
    const int lcol = (tid & 7) * 4;     // 0,4,..,28

    float acc[4][4][4];
#pragma unroll
    for (int mt = 0; mt < 4; mt++)
#pragma unroll
        for (int nt = 0; nt < 4; nt++)
#pragma unroll
            for (int i = 0; i < 4; i++) acc[mt][nt][i] = 0.0f;

    float4 ra[4], rb[4];
#pragma unroll
    for (int i = 0; i < 4; i++) {
        ra[i] = *(const float4*)(A + (size_t)(bm + lrow + i * 32) * K + lcol);
        rb[i] = *(const float4*)(B + (size_t)(bn + lrow + i * 32) * K + lcol);
    }

    for (int k0 = 0; k0 < K; k0 += 32) {
        __syncthreads();
#pragma unroll
        for (int i = 0; i < 4; i++) {
            uint32_t* ap = &As[lrow + i * 32][lcol];
            ap[0] = f2tf32(ra[i].x); ap[1] = f2tf32(ra[i].y);
            ap[2] = f2tf32(ra[i].z); ap[3] = f2tf32(ra[i].w);
            uint32_t* bp = &Bs[lrow + i * 32][lcol];
            bp[0] = f2tf32(rb[i].x); bp[1] = f2tf32(rb[i].y);
            bp[2] = f2tf32(rb[i].z); bp[3] = f2tf32(rb[i].w);
        }
        __syncthreads();

        if (k0 + 32 < K) {
#pragma unroll
            for (int i = 0; i < 4; i++) {
                ra[i] = *(const float4*)(A + (size_t)(bm + lrow + i * 32) * K + k0 + 32 + lcol);
                rb[i] = *(const float4*)(B + (size_t)(bn + lrow + i * 32) * K + k0 + 32 + lcol);
            }
        }

#pragma unroll
        for (int ks = 0; ks < 4; ks++) {
            const int kc = ks * 8;
            uint32_t afrag[4][4];
            uint32_t bfrag[4][2];
#pragma unroll
            for (int mt = 0; mt < 4; mt++) {
                int r0 = wm + mt * 16 + g;
                afrag[mt][0] = As[r0][kc + tg];
                afrag[mt][1] = As[r0 + 8][kc + tg];
                afrag[mt][2] = As[r0][kc + tg + 4];
                afrag[mt][3] = As[r0 + 8][kc + tg + 4];
            }
#pragma unroll
            for (int nt = 0; nt < 4; nt++) {
                int c0 = wn + nt * 8 + g;
                bfrag[nt][0] = Bs[c0][kc + tg];
                bfrag[nt][1] = Bs[c0][kc + tg + 4];
            }
#pragma unroll
            for (int mt = 0; mt < 4; mt++)
#pragma unroll
                for (int nt = 0; nt < 4; nt++)
                    mma_tf32(acc[mt][nt], afrag[mt], bfrag[nt]);
        }
    }

    // Epilogue
#pragma unroll
    for (int mt = 0; mt < 4; mt++) {
#pragma unroll
        for (int nt = 0; nt < 4; nt++) {
            int row0 = bm + wm + mt * 16 + g;
            int col  = bn + wn + nt * 8 + 2 * tg;
            float b0 = 0.0f, b1 = 0.0f;
            if (bias != nullptr) { b0 = bias[col]; b1 = bias[col + 1]; }
            float2 v0, v1;
            v0.x = acc[mt][nt][0] + b0; v0.y = acc[mt][nt][1] + b1;
            v1.x = acc[mt][nt][2] + b0; v1.y = acc[mt][nt][3] + b1;
            *(float2*)(C + (size_t)row0 * N + col)       = v0;
            *(float2*)(C + (size_t)(row0 + 8) * N + col) = v1;
        }
    }
}

// ---------------------------------------------------------------------------
// Flash attention, fp32 SIMT (unchanged from R1).
// ---------------------------------------------------------------------------
__global__ __launch_bounds__(256) void attn_kernel(const float* __restrict__ qkv,
                                                   const int* __restrict__ pmask,
                                                   float* __restrict__ xout)
{
    __shared__ float Qs[64][68];
    __shared__ float Ks[64][36];
    __shared__ float Vs[32][68];
    __shared__ float Ps[32][68];
    __shared__ float mk[32];

    const int t     = threadIdx.x;
    const int qbase = blockIdx.x * 64;
    const int h     = blockIdx.y;
    const int b     = blockIdx.z;

    {
        int r  = t >> 2;
        int d0 = (t & 3) * 16;
        const float* qp = qkv + (size_t)(b * SEQN + qbase + r) * (3 * DIMC) + h * DH + d0;
#pragma unroll
        for (int ii = 0; ii < 4; ii++) {
            float4 v = *(const float4*)(qp + ii * 4);
            int d = d0 + ii * 4;
            Qs[d + 0][r] = v.x; Qs[d + 1][r] = v.y;
            Qs[d + 2][r] = v.z; Qs[d + 3][r] = v.w;
        }
    }

    const int ty = t >> 4;
    const int tx = t & 15;

    float m_old[4], l[4], o[4][4];
#pragma unroll
    for (int i = 0; i < 4; i++) {
        m_old[i] = -3.0e38f;
        l[i] = 0.0f;
#pragma unroll
        for (int j = 0; j < 4; j++) o[i][j] = 0.0f;
    }

    for (int kb = 0; kb < SEQN; kb += 32) {
        __syncthreads();
        {
            int c  = t >> 3;
            int d0 = (t & 7) * 8;
            const float* kp = qkv + (size_t)(b * SEQN + kb + c) * (3 * DIMC) + DIMC + h * DH + d0;
#pragma unroll
            for (int ii = 0; ii < 2; ii++) {
                float4 v = *(const float4*)(kp + ii * 4);
                int d = d0 + ii * 4;
                Ks[d + 0][c] = v.x; Ks[d + 1][c] = v.y;
                Ks[d + 2][c] = v.z; Ks[d + 3][c] = v.w;
            }
        }
        {
            int kk = t >> 3;
            int d0 = (t & 7) * 8;
            const float* vp = qkv + (size_t)(b * SEQN + kb + kk) * (3 * DIMC) + 2 * DIMC + h * DH + d0;
            *(float4*)&Vs[kk][d0]     = *(const float4*)vp;
            *(float4*)&Vs[kk][d0 + 4] = *(const float4*)(vp + 4);
        }
        if (t < 32) mk[t] = (pmask[b * SEQN + kb + t] > 0) ? 1.0f : 0.0f;
        __syncthreads();

        float s[4][2];
#pragma unroll
        for (int i = 0; i < 4; i++) { s[i][0] = 0.0f; s[i][1] = 0.0f; }
#pragma unroll 16
        for (int d = 0; d < 64; d++) {
            float a[4];
            *(float4*)a = *(const float4*)&Qs[d][ty * 4];
            float k0 = Ks[d][tx * 2];
            float k1 = Ks[d][tx * 2 + 1];
#pragma unroll
            for (int i = 0; i < 4; i++) {
                s[i][0] += a[i] * k0;
                s[i][1] += a[i] * k1;
            }
        }

        const float mv0 = mk[tx * 2];
        const float mv1 = mk[tx * 2 + 1];
#pragma unroll
        for (int i = 0; i < 4; i++) {
            s[i][0] = (mv0 > 0.5f) ? MASK_VAL : s[i][0] * SCALE;
            s[i][1] = (mv1 > 0.5f) ? MASK_VAL : s[i][1] * SCALE;
        }

#pragma unroll
        for (int i = 0; i < 4; i++) {
            float mt = fmaxf(s[i][0], s[i][1]);
#pragma unroll
            for (int off = 8; off >= 1; off >>= 1)
                mt = fmaxf(mt, __shfl_xor_sync(0xffffffffu, mt, off, 16));
            float mn    = fmaxf(m_old[i], mt);
            float alpha = __expf(m_old[i] - mn);
            float p0 = __expf(s[i][0] - mn);
            float p1 = __expf(s[i][1] - mn);
            float ls = p0 + p1;
#pragma unroll
            for (int off = 8; off >= 1; off >>= 1)
                ls += __shfl_xor_sync(0xffffffffu, ls, off, 16);
            l[i]     = l[i] * alpha + ls;
            m_old[i] = mn;
#pragma unroll
            for (int j = 0; j < 4; j++) o[i][j] *= alpha;
            Ps[tx * 2 + 0][ty * 4 + i] = p0;
            Ps[tx * 2 + 1][ty * 4 + i] = p1;
        }
        __syncthreads();

#pragma unroll 8
        for (int k2 = 0; k2 < 32; k2++) {
            float p[4], v[4];
            *(float4*)p = *(const float4*)&Ps[k2][ty * 4];
            *(float4*)v = *(const float4*)&Vs[k2][tx * 4];
#pragma unroll
            for (int i = 0; i < 4; i++)
#pragma unroll
                for (int j = 0; j < 4; j++)
                    o[i][j] += p[i] * v[j];
        }
    }

#pragma unroll
    for (int i = 0; i < 4; i++) {
        float inv = 1.0f / l[i];
        int r = qbase + ty * 4 + i;
        float4 v;
        v.x = o[i][0] * inv; v.y = o[i][1] * inv;
        v.z = o[i][2] * inv; v.w = o[i][3] * inv;
        *(float4*)(xout + ((size_t)(b * SEQN + r) * HEADS + h) * DH + tx * 4) = v;
    }
}

// ---------------------------------------------------------------------------
extern "C" void kernel_launch(void* const* d_in, const int* in_sizes, int n_in,
                              void* d_out, int out_size)
{
    const float* x     = (const float*)d_in[0];
    const float* Wqkv  = (const float*)d_in[1];
    const float* Wfc   = (const float*)d_in[2];
    const float* bfc   = (const float*)d_in[3];
    const int*   pmask = (const int*)d_in[4];
    float* out = (float*)d_out;

    float *qkv, *xa;
    cudaGetSymbolAddress((void**)&qkv, g_qkv);
    cudaGetSymbolAddress((void**)&xa, g_x);

    const int M = BATCHB * SEQN;  // 8192

    // 1) qkv = X @ Wqkv^T   (M x 3072), TF32 tensor cores
    gemm_nt_tf32<<<dim3(3 * DIMC / 128, M / 128), 256>>>(x, Wqkv, qkv, nullptr, M, 3 * DIMC, DIMC);

    // 2) flash attention -> xa (M x 1024, [b,n,h,d])
    attn_kernel<<<dim3(SEQN / 64, HEADS, BATCHB), 256>>>(qkv, pmask, xa);

    // 3) out = xa @ Wfc^T + b_fc, TF32 tensor cores
    gemm_nt_tf32<<<dim3(DIMC / 128, M / 128), 256>>>(xa, Wfc, out, bfc, M, DIMC, DIMC);
}

// round 4
// speedup vs baseline: 5.0339x; 3.6337x over previous
#include <cuda_runtime.h>
#include <cuda_fp16.h>
#include <cstdint>

#define DIMC 1024
#define HEADS 16
#define DH 64
#define BATCHB 4
#define SEQN 2048
#define SCALE 0.125f
#define LOG2E 1.4426950408889634f

// Scratch (no allocations allowed)
__device__ float g_qkv[(size_t)BATCHB * SEQN * 3 * DIMC];
__device__ float g_x[(size_t)BATCHB * SEQN * DIMC];

// ---------------- small PTX helpers ----------------
__device__ __forceinline__ uint32_t f2tf32(float x) {
    uint32_t r;
    asm("cvt.rna.tf32.f32 %0, %1;" : "=r"(r) : "f"(x));
    return r;
}
__device__ __forceinline__ void mma_tf32(float* d, const uint32_t* a, const uint32_t* b) {
    asm volatile(
        "mma.sync.aligned.m16n8k8.row.col.f32.tf32.tf32.f32 "
        "{%0,%1,%2,%3}, {%4,%5,%6,%7}, {%8,%9}, {%0,%1,%2,%3};"
        : "+f"(d[0]), "+f"(d[1]), "+f"(d[2]), "+f"(d[3])
        : "r"(a[0]), "r"(a[1]), "r"(a[2]), "r"(a[3]),
          "r"(b[0]), "r"(b[1]));
}
__device__ __forceinline__ void mma16816(float* d, const uint32_t* a, uint32_t b0, uint32_t b1) {
    asm volatile(
        "mma.sync.aligned.m16n8k16.row.col.f32.f16.f16.f32 "
        "{%0,%1,%2,%3}, {%4,%5,%6,%7}, {%8,%9}, {%0,%1,%2,%3};"
        : "+f"(d[0]), "+f"(d[1]), "+f"(d[2]), "+f"(d[3])
        : "r"(a[0]), "r"(a[1]), "r"(a[2]), "r"(a[3]),
          "r"(b0), "r"(b1));
}
__device__ __forceinline__ void ldsm_x4_t(uint32_t& r0, uint32_t& r1, uint32_t& r2, uint32_t& r3,
                                          uint32_t addr) {
    asm volatile("ldmatrix.sync.aligned.m8n8.x4.trans.shared.b16 {%0,%1,%2,%3}, [%4];"
                 : "=r"(r0), "=r"(r1), "=r"(r2), "=r"(r3) : "r"(addr));
}
__device__ __forceinline__ float ex2f(float x) {
    float y;
    asm("ex2.approx.ftz.f32 %0, %1;" : "=f"(y) : "f"(x));
    return y;
}
__device__ __forceinline__ uint32_t packh2(float lo, float hi) {
    __half2 h = __floats2half2_rn(lo, hi);
    return *(uint32_t*)&h;
}

// ---------------------------------------------------------------------------
// C[m,n] = sum_k A[m,k]*B[n,k] (+bias).  TF32 tensor-core version (R3).
// ---------------------------------------------------------------------------
__global__ __launch_bounds__(256) void gemm_nt_tf32(const float* __restrict__ A,
                                                    const float* __restrict__ B,
                                                    float* __restrict__ C,
                                                    const float* __restrict__ bias,
                                                    int M, int N, int K)
{
    __shared__ uint32_t As[128][36];
    __shared__ uint32_t Bs[128][36];

    const int tid  = threadIdx.x;
    const int wid  = tid >> 5;
    const int lane = tid & 31;
    const int g    = lane >> 2;
    const int tg   = lane & 3;
    const int bm   = blockIdx.y * 128;
    const int bn   = blockIdx.x * 128;
    const int wm   = (wid >> 2) * 64;
    const int wn   = (wid & 3) * 32;

    const int lrow = tid >> 3;
    const int lcol = (tid & 7) * 4;

    float acc[4][4][4];
#pragma unroll
    for (int mt = 0; mt < 4; mt++)
#pragma unroll
        for (int nt = 0; nt < 4; nt++)
#pragma unroll
            for (int i = 0; i < 4; i++) acc[mt][nt][i] = 0.0f;

    float4 ra[4], rb[4];
#pragma unroll
    for (int i = 0; i < 4; i++) {
        ra[i] = *(const float4*)(A + (size_t)(bm + lrow + i * 32) * K + lcol);
        rb[i] = *(const float4*)(B + (size_t)(bn + lrow + i * 32) * K + lcol);
    }

    for (int k0 = 0; k0 < K; k0 += 32) {
        __syncthreads();
#pragma unroll
        for (int i = 0; i < 4; i++) {
            uint32_t* ap = &As[lrow + i * 32][lcol];
            ap[0] = f2tf32(ra[i].x); ap[1] = f2tf32(ra[i].y);
            ap[2] = f2tf32(ra[i].z); ap[3] = f2tf32(ra[i].w);
            uint32_t* bp = &Bs[lrow + i * 32][lcol];
            bp[0] = f2tf32(rb[i].x); bp[1] = f2tf32(rb[i].y);
            bp[2] = f2tf32(rb[i].z); bp[3] = f2tf32(rb[i].w);
        }
        __syncthreads();

        if (k0 + 32 < K) {
#pragma unroll
            for (int i = 0; i < 4; i++) {
                ra[i] = *(const float4*)(A + (size_t)(bm + lrow + i * 32) * K + k0 + 32 + lcol);
                rb[i] = *(const float4*)(B + (size_t)(bn + lrow + i * 32) * K + k0 + 32 + lcol);
            }
        }

#pragma unroll
        for (int ks = 0; ks < 4; ks++) {
            const int kc = ks * 8;
            uint32_t afrag[4][4];
            uint32_t bfrag[4][2];
#pragma unroll
            for (int mt = 0; mt < 4; mt++) {
                int r0 = wm + mt * 16 + g;
                afrag[mt][0] = As[r0][kc + tg];
                afrag[mt][1] = As[r0 + 8][kc + tg];
                afrag[mt][2] = As[r0][kc + tg + 4];
                afrag[mt][3] = As[r0 + 8][kc + tg + 4];
            }
#pragma unroll
            for (int nt = 0; nt < 4; nt++) {
                int c0 = wn + nt * 8 + g;
                bfrag[nt][0] = Bs[c0][kc + tg];
                bfrag[nt][1] = Bs[c0][kc + tg + 4];
            }
#pragma unroll
            for (int mt = 0; mt < 4; mt++)
#pragma unroll
                for (int nt = 0; nt < 4; nt++)
                    mma_tf32(acc[mt][nt], afrag[mt], bfrag[nt]);
        }
    }

#pragma unroll
    for (int mt = 0; mt < 4; mt++) {
#pragma unroll
        for (int nt = 0; nt < 4; nt++) {
            int row0 = bm + wm + mt * 16 + g;
            int col  = bn + wn + nt * 8 + 2 * tg;
            float b0 = 0.0f, b1 = 0.0f;
            if (bias != nullptr) { b0 = bias[col]; b1 = bias[col + 1]; }
            float2 v0, v1;
            v0.x = acc[mt][nt][0] + b0; v0.y = acc[mt][nt][1] + b1;
            v1.x = acc[mt][nt][2] + b0; v1.y = acc[mt][nt][3] + b1;
            *(float2*)(C + (size_t)row0 * N + col)       = v0;
            *(float2*)(C + (size_t)(row0 + 8) * N + col) = v1;
        }
    }
}

// ---------------------------------------------------------------------------
// Flash attention with fp16 tensor cores.
// Block = (b, h, 128 q-rows). 8 warps, each owns 16 q-rows.
// KV tiles of 64 keys staged in smem as fp16 (stride 72 halves).
// S-mma: Q (reg A-frags) x K (LDS B-frags). P stays in registers
// (S C-frag layout == PV A-frag layout). V B-frags via ldmatrix.x4.trans.
// ---------------------------------------------------------------------------
__global__ __launch_bounds__(256, 2) void attn_fa16(const float* __restrict__ qkv,
                                                    const int* __restrict__ pmask,
                                                    float* __restrict__ xout)
{
    __shared__ __half Ks[64][72];
    __shared__ __half Vs[64][72];
    __shared__ float  mb[64];

    const int t    = threadIdx.x;
    const int w    = t >> 5;
    const int lane = t & 31;
    const int g    = lane >> 2;
    const int tg   = lane & 3;
    const int h    = blockIdx.y;
    const int b    = blockIdx.z;
    const int qbase = blockIdx.x * 128;

    const float SC2 = SCALE * LOG2E;

    // ---- Q fragments (held in registers for the whole kernel) ----
    uint32_t qa[4][4];
    {
        const int qr = b * SEQN + qbase + w * 16 + g;
        const float* q0 = qkv + (size_t)qr * (3 * DIMC) + h * DH;
        const float* q8 = q0 + (size_t)8 * (3 * DIMC);
#pragma unroll
        for (int kt = 0; kt < 4; kt++) {
            float2 v0 = *(const float2*)(q0 + kt * 16 + 2 * tg);
            float2 v1 = *(const float2*)(q8 + kt * 16 + 2 * tg);
            float2 v2 = *(const float2*)(q0 + kt * 16 + 8 + 2 * tg);
            float2 v3 = *(const float2*)(q8 + kt * 16 + 8 + 2 * tg);
            qa[kt][0] = packh2(v0.x, v0.y);
            qa[kt][1] = packh2(v1.x, v1.y);
            qa[kt][2] = packh2(v2.x, v2.y);
            qa[kt][3] = packh2(v3.x, v3.y);
        }
    }

    // ldmatrix per-lane source row/col for V
    const int lr = ((lane >> 3) & 1) * 8 + (lane & 7);
    const int lc = (lane >> 4) * 8;
    const uint32_t vbase = (uint32_t)__cvta_generic_to_shared(&Vs[0][0]);

    // Online softmax state
    float m0 = -1e30f, m1 = -1e30f, l0 = 0.0f, l1 = 0.0f;
    float of[8][4];
#pragma unroll
    for (int nt = 0; nt < 8; nt++)
#pragma unroll
        for (int i = 0; i < 4; i++) of[nt][i] = 0.0f;

    // KV staging thread mapping: lane -> d, warp -> key rows
    const int dcol = (lane) * 2;       // 0..62
    const int krow = w;                // 0..7 -> keys w, w+8, ..., w+56

    for (int kb = 0; kb < SEQN; kb += 64) {
        __syncthreads();
        // ---- stage K, V (fp16) and mask bias ----
#pragma unroll
        for (int j = 0; j < 8; j++) {
            const int key = krow + j * 8;
            const float* kp = qkv + (size_t)(b * SEQN + kb + key) * (3 * DIMC) + DIMC + h * DH + dcol;
            float2 kv = *(const float2*)kp;
            float2 vv = *(const float2*)(kp + DIMC);
            *(uint32_t*)&Ks[key][dcol] = packh2(kv.x, kv.y);
            *(uint32_t*)&Vs[key][dcol] = packh2(vv.x, vv.y);
        }
        if (t < 64) mb[t] = (pmask[b * SEQN + kb + t] > 0) ? -1e9f : 0.0f;
        __syncthreads();

        // ---- S = Q K^T (16 x 64 per warp) ----
        float sf[8][4];
#pragma unroll
        for (int nt = 0; nt < 8; nt++)
#pragma unroll
            for (int i = 0; i < 4; i++) sf[nt][i] = 0.0f;

#pragma unroll
        for (int kt = 0; kt < 4; kt++) {
#pragma unroll
            for (int nt = 0; nt < 8; nt++) {
                uint32_t kb0 = *(const uint32_t*)&Ks[8 * nt + g][16 * kt + 2 * tg];
                uint32_t kb1 = *(const uint32_t*)&Ks[8 * nt + g][16 * kt + 2 * tg + 8];
                mma16816(sf[nt], qa[kt], kb0, kb1);
            }
        }

        // ---- softmax (base-2 domain) ----
        float mt0 = -1e30f, mt1 = -1e30f;
#pragma unroll
        for (int nt = 0; nt < 8; nt++) {
            float2 bb = *(const float2*)&mb[8 * nt + 2 * tg];
            sf[nt][0] = fmaf(sf[nt][0], SC2, bb.x);
            sf[nt][1] = fmaf(sf[nt][1], SC2, bb.y);
            sf[nt][2] = fmaf(sf[nt][2], SC2, bb.x);
            sf[nt][3] = fmaf(sf[nt][3], SC2, bb.y);
            mt0 = fmaxf(mt0, fmaxf(sf[nt][0], sf[nt][1]));
            mt1 = fmaxf(mt1, fmaxf(sf[nt][2], sf[nt][3]));
        }
        mt0 = fmaxf(mt0, __shfl_xor_sync(0xffffffffu, mt0, 1));
        mt0 = fmaxf(mt0, __shfl_xor_sync(0xffffffffu, mt0, 2));
        mt1 = fmaxf(mt1, __shfl_xor_sync(0xffffffffu, mt1, 1));
        mt1 = fmaxf(mt1, __shfl_xor_sync(0xffffffffu, mt1, 2));

        const float mn0 = fmaxf(m0, mt0);
        const float mn1 = fmaxf(m1, mt1);
        const float alpha0 = ex2f(m0 - mn0);
        const float alpha1 = ex2f(m1 - mn1);
        m0 = mn0; m1 = mn1;

        float ls0 = 0.0f, ls1 = 0.0f;
        uint32_t pa[4][4];
#pragma unroll
        for (int nt = 0; nt < 8; nt++) {
            float p0 = ex2f(sf[nt][0] - mn0);
            float p1 = ex2f(sf[nt][1] - mn0);
            float p2 = ex2f(sf[nt][2] - mn1);
            float p3 = ex2f(sf[nt][3] - mn1);
            ls0 += p0 + p1;
            ls1 += p2 + p3;
            const int kt  = nt >> 1;
            const int hi  = (nt & 1) ? 2 : 0;
            pa[kt][hi + 0] = packh2(p0, p1);
            pa[kt][hi + 1] = packh2(p2, p3);
        }
        l0 = l0 * alpha0 + ls0;
        l1 = l1 * alpha1 + ls1;
#pragma unroll
        for (int nt = 0; nt < 8; nt++) {
            of[nt][0] *= alpha0;
            of[nt][1] *= alpha0;
            of[nt][2] *= alpha1;
            of[nt][3] *= alpha1;
        }

        // ---- O += P V ----
#pragma unroll
        for (int kt = 0; kt < 4; kt++) {
#pragma unroll
            for (int c = 0; c < 8; c += 2) {
                uint32_t r0, r1, r2, r3;
                uint32_t addr = vbase + (uint32_t)(((16 * kt + lr) * 72 + lc + 8 * c) * 2);
                ldsm_x4_t(r0, r1, r2, r3, addr);
                mma16816(of[c],     pa[kt], r0, r1);
                mma16816(of[c + 1], pa[kt], r2, r3);
            }
        }
    }

    // ---- epilogue ----
    l0 += __shfl_xor_sync(0xffffffffu, l0, 1);
    l0 += __shfl_xor_sync(0xffffffffu, l0, 2);
    l1 += __shfl_xor_sync(0xffffffffu, l1, 1);
    l1 += __shfl_xor_sync(0xffffffffu, l1, 2);
    const float inv0 = 1.0f / l0;
    const float inv1 = 1.0f / l1;

    const int qr = qbase + w * 16 + g;
    float* o0 = xout + ((size_t)(b * SEQN + qr) * HEADS + h) * DH;
    float* o8 = xout + ((size_t)(b * SEQN + qr + 8) * HEADS + h) * DH;
#pragma unroll
    for (int nt = 0; nt < 8; nt++) {
        float2 v0, v1;
        v0.x = of[nt][0] * inv0; v0.y = of[nt][1] * inv0;
        v1.x = of[nt][2] * inv1; v1.y = of[nt][3] * inv1;
        *(float2*)(o0 + 8 * nt + 2 * tg) = v0;
        *(float2*)(o8 + 8 * nt + 2 * tg) = v1;
    }
}

// ---------------------------------------------------------------------------
extern "C" void kernel_launch(void* const* d_in, const int* in_sizes, int n_in,
                              void* d_out, int out_size)
{
    const float* x     = (const float*)d_in[0];
    const float* Wqkv  = (const float*)d_in[1];
    const float* Wfc   = (const float*)d_in[2];
    const float* bfc   = (const float*)d_in[3];
    const int*   pmask = (const int*)d_in[4];
    float* out = (float*)d_out;

    float *qkv, *xa;
    cudaGetSymbolAddress((void**)&qkv, g_qkv);
    cudaGetSymbolAddress((void**)&xa, g_x);

    const int M = BATCHB * SEQN;  // 8192

    // 1) qkv = X @ Wqkv^T   (M x 3072), TF32 tensor cores
    gemm_nt_tf32<<<dim3(3 * DIMC / 128, M / 128), 256>>>(x, Wqkv, qkv, nullptr, M, 3 * DIMC, DIMC);

    // 2) flash attention (fp16 tensor cores) -> xa (M x 1024, [b,n,h,d])
    attn_fa16<<<dim3(SEQN / 128, HEADS, BATCHB), 256>>>(qkv, pmask, xa);

    // 3) out = xa @ Wfc^T + b_fc, TF32 tensor cores
    gemm_nt_tf32<<<dim3(DIMC / 128, M / 128), 256>>>(xa, Wfc, out, bfc, M, DIMC, DIMC);
}